// round 1
// baseline (speedup 1.0000x reference)
#include <cuda_runtime.h>

// Problem constants
#define BATCH    8
#define S_BYTES  8192
#define NUM_EMB  384
#define BYTE_DIM 128
#define EMB_DIM  1024
#define NUM_TOK  2048
#define SCALE_F  11.313708498984761f  // sqrt(128)

// Scratch for pooled token embeddings: [B, NUM_TOK, BYTE_DIM] fp32 (8.4 MB)
__device__ float g_grouped[BATCH * NUM_TOK * BYTE_DIM];

// ---------------------------------------------------------------------------
// Kernel 1: embedding gather + ragged mean pool (segments are sorted per row).
// grid = (NUM_TOK, BATCH), block = 128 (one thread per byte_dim channel).
// ---------------------------------------------------------------------------
__global__ void pool_kernel(const int* __restrict__ x,
                            const int* __restrict__ byte_groups,
                            const float* __restrict__ emb) {
    const int t = blockIdx.x;   // token id in [0, NUM_TOK)
    const int b = blockIdx.y;   // batch
    const int d = threadIdx.x;  // channel in [0, BYTE_DIM)

    const int* __restrict__ row = byte_groups + (size_t)b * S_BYTES;

    // lower_bound(row, t): first index with row[i] >= t
    int lo = 0, hi = S_BYTES;
    while (lo < hi) {
        int m = (lo + hi) >> 1;
        if (row[m] < t) lo = m + 1; else hi = m;
    }
    const int start = lo;
    // lower_bound(row, t+1), continuing from 'start'
    hi = S_BYTES;
    while (lo < hi) {
        int m = (lo + hi) >> 1;
        if (row[m] < t + 1) lo = m + 1; else hi = m;
    }
    const int end = lo;

    const int* __restrict__ xr = x + (size_t)b * S_BYTES;
    float acc = 0.0f;
    for (int s = start; s < end; ++s) {
        int e = xr[s];  // broadcast load, L1/L2 resident
        acc += emb[(size_t)e * BYTE_DIM + d];  // coalesced 512B row
    }
    const int cnt = end - start;
    const float sc = SCALE_F / (float)(cnt > 0 ? cnt : 1);
    g_grouped[(((size_t)b * NUM_TOK) + t) * BYTE_DIM + d] = acc * sc;
}

// ---------------------------------------------------------------------------
// Kernel 2: fp32 GEMM  out[m][n] = sum_k grouped[m][k] * W[n][k]
// M = BATCH*NUM_TOK = 16384, N = EMB_DIM = 1024, K = BYTE_DIM = 128.
// Tile 64x64, BK=64, 256 threads, 4x4 microtile per thread.
// Smem stored transposed [k][m] / [k][n] with pitch 65:
//   - transpose stores: lanes vary k by 1 -> bank stride 65 % 32 = 1 -> conflict-free
//   - A compute reads broadcast across tx; W reads are <=2-way conflicted.
// ---------------------------------------------------------------------------
#define BM 64
#define BN 64
#define BK 64
#define SPITCH 65

__global__ __launch_bounds__(256) void gemm_kernel(const float* __restrict__ W,
                                                   float* __restrict__ out) {
    __shared__ float As[BK][SPITCH];  // [k][m]
    __shared__ float Ws[BK][SPITCH];  // [k][n]

    const int bn = blockIdx.x;  // 0..15
    const int bm = blockIdx.y;  // 0..255
    const int tid = threadIdx.x;
    const int tx = tid & 15;        // col group
    const int ty = tid >> 4;        // row group
    const int m0 = ty * 4;
    const int n0 = tx * 4;

    const float* __restrict__ A  = g_grouped + (size_t)(bm * BM) * BYTE_DIM;
    const float* __restrict__ Wt = W         + (size_t)(bn * BN) * BYTE_DIM;

    float acc[4][4] = {};

    for (int kb = 0; kb < BYTE_DIM; kb += BK) {
        // Cooperative transposed tile load: 4096 elems each, 16 per thread.
        // f: k fastest -> global reads fully coalesced (k is contiguous dim).
        #pragma unroll
        for (int i = 0; i < 16; ++i) {
            int f = tid + i * 256;
            int k = f & 63;
            int r = f >> 6;
            As[k][r] = A [(size_t)r * BYTE_DIM + kb + k];
            Ws[k][r] = Wt[(size_t)r * BYTE_DIM + kb + k];
        }
        __syncthreads();

        #pragma unroll 8
        for (int k = 0; k < BK; ++k) {
            float a[4], w[4];
            #pragma unroll
            for (int j = 0; j < 4; ++j) a[j] = As[k][m0 + j];
            #pragma unroll
            for (int j = 0; j < 4; ++j) w[j] = Ws[k][n0 + j];
            #pragma unroll
            for (int i = 0; i < 4; ++i)
                #pragma unroll
                for (int j = 0; j < 4; ++j)
                    acc[i][j] = fmaf(a[i], w[j], acc[i][j]);
        }
        __syncthreads();
    }

    // Write 4x4 microtile, vectorized along n.
    #pragma unroll
    for (int i = 0; i < 4; ++i) {
        float4 v = make_float4(acc[i][0], acc[i][1], acc[i][2], acc[i][3]);
        *reinterpret_cast<float4*>(
            out + (size_t)(bm * BM + m0 + i) * EMB_DIM + bn * BN + n0) = v;
    }
}

// ---------------------------------------------------------------------------
// Launch
// ---------------------------------------------------------------------------
extern "C" void kernel_launch(void* const* d_in, const int* in_sizes, int n_in,
                              void* d_out, int out_size) {
    const int*   x    = (const int*)  d_in[0];  // [B, S_BYTES] int32
    const int*   bg   = (const int*)  d_in[1];  // [B, S_BYTES] int32 (sorted per row)
    const float* emb  = (const float*)d_in[2];  // [NUM_EMB, BYTE_DIM] fp32
    const float* wout = (const float*)d_in[3];  // [EMB_DIM, BYTE_DIM] fp32
    float* out = (float*)d_out;                 // [B, NUM_TOK, EMB_DIM] fp32

    (void)in_sizes; (void)n_in; (void)out_size;

    dim3 pgrid(NUM_TOK, BATCH);
    pool_kernel<<<pgrid, BYTE_DIM>>>(x, bg, emb);

    dim3 ggrid(EMB_DIM / BN, (BATCH * NUM_TOK) / BM);
    gemm_kernel<<<ggrid, 256>>>(wout, out);
}

// round 2
// speedup vs baseline: 2.3050x; 2.3050x over previous
#include <cuda_runtime.h>

// Problem constants
#define BATCH    8
#define S_BYTES  8192
#define NUM_EMB  384
#define BYTE_DIM 128
#define EMB_DIM  1024
#define NUM_TOK  2048
#define SCALE_F  11.313708498984761f  // sqrt(128)

// proj = SCALE * emb @ W^T : [NUM_EMB, EMB_DIM] fp32 (1.5 MB, L2-resident)
__device__ float g_proj[NUM_EMB * EMB_DIM];

// ---------------------------------------------------------------------------
// Kernel 1: tiny GEMM  proj[e][n] = SCALE * sum_k emb[e][k] * W[n][k]
// M = 384, N = 1024, K = 128. 64x64 tiles, 256 threads, 4x4 microtile.
// ---------------------------------------------------------------------------
#define BM 64
#define BN 64
#define BK 64
#define SPITCH 65

__global__ __launch_bounds__(256) void proj_gemm_kernel(const float* __restrict__ emb,
                                                        const float* __restrict__ W) {
    __shared__ float As[BK][SPITCH];  // [k][m]
    __shared__ float Ws[BK][SPITCH];  // [k][n]

    const int bn = blockIdx.x;  // 0..15
    const int bm = blockIdx.y;  // 0..5
    const int tid = threadIdx.x;
    const int tx = tid & 15;
    const int ty = tid >> 4;
    const int m0 = ty * 4;
    const int n0 = tx * 4;

    const float* __restrict__ A  = emb + (size_t)(bm * BM) * BYTE_DIM;
    const float* __restrict__ Wt = W   + (size_t)(bn * BN) * BYTE_DIM;

    float acc[4][4] = {};

    for (int kb = 0; kb < BYTE_DIM; kb += BK) {
        #pragma unroll
        for (int i = 0; i < 16; ++i) {
            int f = tid + i * 256;
            int k = f & 63;
            int r = f >> 6;
            As[k][r] = A [(size_t)r * BYTE_DIM + kb + k];
            Ws[k][r] = Wt[(size_t)r * BYTE_DIM + kb + k];
        }
        __syncthreads();

        #pragma unroll 8
        for (int k = 0; k < BK; ++k) {
            float a[4], w[4];
            #pragma unroll
            for (int j = 0; j < 4; ++j) a[j] = As[k][m0 + j];
            #pragma unroll
            for (int j = 0; j < 4; ++j) w[j] = Ws[k][n0 + j];
            #pragma unroll
            for (int i = 0; i < 4; ++i)
                #pragma unroll
                for (int j = 0; j < 4; ++j)
                    acc[i][j] = fmaf(a[i], w[j], acc[i][j]);
        }
        __syncthreads();
    }

    #pragma unroll
    for (int i = 0; i < 4; ++i) {
        float4 v = make_float4(acc[i][0] * SCALE_F, acc[i][1] * SCALE_F,
                               acc[i][2] * SCALE_F, acc[i][3] * SCALE_F);
        *reinterpret_cast<float4*>(
            g_proj + (size_t)(bm * BM + m0 + i) * EMB_DIM + bn * BN + n0) = v;
    }
}

// ---------------------------------------------------------------------------
// Kernel 2: ragged mean over proj rows (linearity of the projection).
// out[b,t,:] = (1/cnt) * sum_{s in segment} proj[x[b,s], :]
// grid = (NUM_TOK, BATCH), block = 256, each thread owns one float4 (4 chans).
// proj is 1.5 MB -> L2 resident; loop loads are coalesced 4 KB row reads.
// ---------------------------------------------------------------------------
__global__ __launch_bounds__(256) void pool_proj_kernel(const int* __restrict__ x,
                                                        const int* __restrict__ byte_groups,
                                                        float* __restrict__ out) {
    const int t = blockIdx.x;   // token
    const int b = blockIdx.y;   // batch
    const int tid = threadIdx.x;

    const int* __restrict__ row = byte_groups + (size_t)b * S_BYTES;

    // lower_bound(row, t)
    int lo = 0, hi = S_BYTES;
    while (lo < hi) {
        int m = (lo + hi) >> 1;
        if (row[m] < t) lo = m + 1; else hi = m;
    }
    const int start = lo;
    // lower_bound(row, t+1)
    hi = S_BYTES;
    while (lo < hi) {
        int m = (lo + hi) >> 1;
        if (row[m] < t + 1) lo = m + 1; else hi = m;
    }
    const int end = lo;

    const int* __restrict__ xr = x + (size_t)b * S_BYTES;
    const float4* __restrict__ p = reinterpret_cast<const float4*>(g_proj);

    float4 acc = make_float4(0.f, 0.f, 0.f, 0.f);
    for (int s = start; s < end; ++s) {
        int e = xr[s];  // broadcast load
        float4 v = p[(size_t)e * (EMB_DIM / 4) + tid];  // coalesced, L2-hit
        acc.x += v.x; acc.y += v.y; acc.z += v.z; acc.w += v.w;
    }

    const int cnt = end - start;
    const float inv = 1.0f / (float)(cnt > 0 ? cnt : 1);
    acc.x *= inv; acc.y *= inv; acc.z *= inv; acc.w *= inv;

    float4* __restrict__ o = reinterpret_cast<float4*>(out);
    o[(((size_t)b * NUM_TOK) + t) * (EMB_DIM / 4) + tid] = acc;
}

// ---------------------------------------------------------------------------
// Launch
// ---------------------------------------------------------------------------
extern "C" void kernel_launch(void* const* d_in, const int* in_sizes, int n_in,
                              void* d_out, int out_size) {
    const int*   x    = (const int*)  d_in[0];  // [B, S_BYTES] int32
    const int*   bg   = (const int*)  d_in[1];  // [B, S_BYTES] int32 (sorted per row)
    const float* emb  = (const float*)d_in[2];  // [NUM_EMB, BYTE_DIM] fp32
    const float* wout = (const float*)d_in[3];  // [EMB_DIM, BYTE_DIM] fp32
    float* out = (float*)d_out;                 // [B, NUM_TOK, EMB_DIM] fp32

    (void)in_sizes; (void)n_in; (void)out_size;

    dim3 ggrid(EMB_DIM / BN, NUM_EMB / BM);   // (16, 6)
    proj_gemm_kernel<<<ggrid, 256>>>(emb, wout);

    dim3 pgrid(NUM_TOK, BATCH);               // 16384 blocks
    pool_proj_kernel<<<pgrid, 256>>>(x, bg, out);
}

// round 3
// speedup vs baseline: 5.2572x; 2.2808x over previous
#include <cuda_runtime.h>

// Problem constants
#define BATCH    8
#define S_BYTES  8192
#define NUM_EMB  384
#define BYTE_DIM 128
#define EMB_DIM  1024
#define NUM_TOK  2048
#define SCALE_F  11.313708498984761f  // sqrt(128)

// proj = SCALE * emb @ W^T : [NUM_EMB, EMB_DIM] fp32 (1.5 MB, L2-resident)
__device__ float g_proj[NUM_EMB * EMB_DIM];
// Segment starts: g_start[b][t] = first byte index s with byte_groups[b][s] >= t
__device__ int g_start[BATCH][NUM_TOK + 1];

// ---------------------------------------------------------------------------
// Kernel A: tiny GEMM  proj[e][n] = SCALE * sum_k emb[e][k] * W[n][k]
// M=384, N=1024, K=128. 32x32 tiles (384 blocks), full-K smem, one sync.
// ---------------------------------------------------------------------------
#define BM 32
#define BN 32
#define SPITCH 33

__global__ __launch_bounds__(256) void proj_gemm_kernel(const float* __restrict__ emb,
                                                        const float* __restrict__ W) {
    __shared__ float As[BYTE_DIM][SPITCH];  // [k][m]
    __shared__ float Ws[BYTE_DIM][SPITCH];  // [k][n]

    const int bn = blockIdx.x;  // 0..31
    const int bm = blockIdx.y;  // 0..11
    const int tid = threadIdx.x;
    const int tx = tid & 15;        // n group (16)
    const int ty = tid >> 4;        // m group (16)
    const int m0 = ty * 2;
    const int n0 = tx * 2;

    const float* __restrict__ A  = emb + (size_t)(bm * BM) * BYTE_DIM;
    const float* __restrict__ Wt = W   + (size_t)(bn * BN) * BYTE_DIM;

    // Transposed cooperative load of both 32x128 tiles (4096 elems each).
    // f = r*128 + k with k fastest -> coalesced global reads.
    #pragma unroll
    for (int i = 0; i < 16; ++i) {
        int f = tid + i * 256;
        int k = f & 127;
        int r = f >> 7;
        As[k][r] = A [(size_t)r * BYTE_DIM + k];
        Ws[k][r] = Wt[(size_t)r * BYTE_DIM + k];
    }
    __syncthreads();

    float acc[2][2] = {};
    #pragma unroll 8
    for (int k = 0; k < BYTE_DIM; ++k) {
        float a0 = As[k][m0], a1 = As[k][m0 + 1];
        float w0 = Ws[k][n0], w1 = Ws[k][n0 + 1];
        acc[0][0] = fmaf(a0, w0, acc[0][0]);
        acc[0][1] = fmaf(a0, w1, acc[0][1]);
        acc[1][0] = fmaf(a1, w0, acc[1][0]);
        acc[1][1] = fmaf(a1, w1, acc[1][1]);
    }

    #pragma unroll
    for (int i = 0; i < 2; ++i) {
        float2 v = make_float2(acc[i][0] * SCALE_F, acc[i][1] * SCALE_F);
        *reinterpret_cast<float2*>(
            g_proj + (size_t)(bm * BM + m0 + i) * EMB_DIM + bn * BN + n0) = v;
    }
}

// ---------------------------------------------------------------------------
// Kernel B: segment boundaries from the sorted byte_groups rows.
// Thread s writes g_start[b][t] = s for all t in (bg[s-1], bg[s]].
// Thread S_BYTES-1 additionally fills the tail with S_BYTES.
// ---------------------------------------------------------------------------
__global__ __launch_bounds__(256) void seg_bounds_kernel(const int* __restrict__ bg) {
    const int b = blockIdx.y;
    const int s = blockIdx.x * 256 + threadIdx.x;
    const int* __restrict__ row = bg + (size_t)b * S_BYTES;

    const int g  = row[s];
    const int gp = (s == 0) ? -1 : row[s - 1];
    for (int t = gp + 1; t <= g; ++t) g_start[b][t] = s;
    if (s == S_BYTES - 1) {
        for (int t = g + 1; t <= NUM_TOK; ++t) g_start[b][t] = S_BYTES;
    }
}

// ---------------------------------------------------------------------------
// Kernel C: ragged mean over proj rows, warp-per-token.
// out[b,t,:] = (1/cnt) * sum_{s in [start,end)} proj[x[b,s], :]
// grid = (NUM_TOK/8, BATCH), block = 256 (8 warps). Each lane owns 8 float4
// (32 channels), giving 8 independent L2 load chains per gathered byte.
// ---------------------------------------------------------------------------
__global__ __launch_bounds__(256) void pool_proj_kernel(const int* __restrict__ x,
                                                        float* __restrict__ out) {
    const int b    = blockIdx.y;
    const int wid  = threadIdx.x >> 5;
    const int lane = threadIdx.x & 31;
    const int t    = blockIdx.x * 8 + wid;

    const int start = g_start[b][t];
    const int end   = g_start[b][t + 1];

    const int* __restrict__ xr = x + (size_t)b * S_BYTES;
    const float4* __restrict__ p = reinterpret_cast<const float4*>(g_proj);

    float4 acc[8];
    #pragma unroll
    for (int j = 0; j < 8; ++j) acc[j] = make_float4(0.f, 0.f, 0.f, 0.f);

    for (int s = start; s < end; ++s) {
        const int e = xr[s];  // warp-broadcast load
        const float4* __restrict__ pr = p + (size_t)e * (EMB_DIM / 4);
        #pragma unroll
        for (int j = 0; j < 8; ++j) {
            float4 v = pr[lane + 32 * j];  // coalesced 512B per j, L2-hit
            acc[j].x += v.x; acc[j].y += v.y; acc[j].z += v.z; acc[j].w += v.w;
        }
    }

    const int cnt = end - start;
    const float inv = 1.0f / (float)(cnt > 0 ? cnt : 1);

    float4* __restrict__ o =
        reinterpret_cast<float4*>(out) + (((size_t)b * NUM_TOK) + t) * (EMB_DIM / 4);
    #pragma unroll
    for (int j = 0; j < 8; ++j) {
        float4 v = make_float4(acc[j].x * inv, acc[j].y * inv,
                               acc[j].z * inv, acc[j].w * inv);
        o[lane + 32 * j] = v;
    }
}

// ---------------------------------------------------------------------------
// Launch
// ---------------------------------------------------------------------------
extern "C" void kernel_launch(void* const* d_in, const int* in_sizes, int n_in,
                              void* d_out, int out_size) {
    const int*   x    = (const int*)  d_in[0];  // [B, S_BYTES] int32
    const int*   bg   = (const int*)  d_in[1];  // [B, S_BYTES] int32 (sorted per row)
    const float* emb  = (const float*)d_in[2];  // [NUM_EMB, BYTE_DIM] fp32
    const float* wout = (const float*)d_in[3];  // [EMB_DIM, BYTE_DIM] fp32
    float* out = (float*)d_out;                 // [B, NUM_TOK, EMB_DIM] fp32

    (void)in_sizes; (void)n_in; (void)out_size;

    dim3 bgrid(S_BYTES / 256, BATCH);           // 32 x 8 blocks
    seg_bounds_kernel<<<bgrid, 256>>>(bg);

    dim3 ggrid(EMB_DIM / BN, NUM_EMB / BM);     // (32, 12) = 384 blocks
    proj_gemm_kernel<<<ggrid, 256>>>(emb, wout);

    dim3 pgrid(NUM_TOK / 8, BATCH);             // (256, 8) = 2048 blocks
    pool_proj_kernel<<<pgrid, 256>>>(x, out);
}